// round 10
// baseline (speedup 1.0000x reference)
#include <cuda_runtime.h>
#include <cstdint>

// Problem constants
constexpr int NB  = 16;      // batch
constexpr int NS  = 1024;    // seq
constexpr int NIN = 512;     // in features
constexpr int NOUT= 512;     // out features
constexpr int NH  = 8;       // heads
constexpr int NDH = 64;      // head dim
constexpr int NM  = NB * NS; // 16384 rows

// Scratch (device globals). ~112 MB total.
__device__ float g_q[(size_t)NH * NB * NS * NDH];   // 16 MB
__device__ float g_k[(size_t)NH * NB * NS * NDH];   // 16 MB
__device__ float g_v[(size_t)NH * NB * NS * NDH];   // 16 MB
__device__ float g_R[(size_t)NH * NS * NS];         // 32 MB: 1/sum_b E; later reused as pre-LN y
__device__ float g_att[(size_t)NM * NOUT];          // 32 MB: concat heads

// ---- tf32 mma.sync helpers -------------------------------------------------
__device__ __forceinline__ uint32_t cvt_tf32(float x) {
    uint32_t r;
    asm("cvt.rna.tf32.f32 %0, %1;" : "=r"(r) : "f"(x));
    return r;
}
// D(16x8,f32) += A(16x8,tf32,row) * B(8x8,tf32,col)
__device__ __forceinline__ void mma8(float* c, const uint32_t* a, const uint32_t* b) {
    asm("mma.sync.aligned.m16n8k8.row.col.f32.tf32.tf32.f32 "
        "{%0,%1,%2,%3}, {%4,%5,%6,%7}, {%8,%9}, {%0,%1,%2,%3};"
        : "+f"(c[0]), "+f"(c[1]), "+f"(c[2]), "+f"(c[3])
        : "r"(a[0]), "r"(a[1]), "r"(a[2]), "r"(a[3]), "r"(b[0]), "r"(b[1]));
}
// A fragment from As[row][k], row stride ld (ld % 32 == 4 -> conflict-free)
__device__ __forceinline__ void ldA(uint32_t* a, const uint32_t* As, int ld,
                                    int row0, int ks, int lane) {
    const uint32_t* p = As + (row0 + (lane >> 2)) * ld + ks + (lane & 3);
    a[0] = p[0]; a[1] = p[8 * ld]; a[2] = p[4]; a[3] = p[8 * ld + 4];
}
// B fragment from Bs[n][k], row stride ld
__device__ __forceinline__ void ldBnk(uint32_t* b, const uint32_t* Bs, int ld,
                                      int n0, int ks, int lane) {
    const uint32_t* p = Bs + (n0 + (lane >> 2)) * ld + ks + (lane & 3);
    b[0] = p[0]; b[1] = p[4];
}
// B fragment from Bs[k][n], row stride ldn (ldn % 32 == 4)
__device__ __forceinline__ void ldBkn(uint32_t* b, const uint32_t* Bs, int ldn,
                                      int n0, int ks, int lane) {
    const uint32_t* p = Bs + (ks + (lane & 3)) * ldn + n0 + (lane >> 2);
    b[0] = p[0]; b[1] = p[4 * ldn];
}

// ---------------------------------------------------------------------------
// K1: QKV projection (tf32 mma).  Block 128x128, BK=32, warp tile 64x32.
// ---------------------------------------------------------------------------
__global__ void __launch_bounds__(256) k_qkv(const float* __restrict__ x,
                      const float* __restrict__ wq,
                      const float* __restrict__ wk,
                      const float* __restrict__ wv) {
    __shared__ __align__(16) uint32_t As[128 * 36];   // x tile  [m][k]
    __shared__ __align__(16) uint32_t Bs[32 * 132];   // w tile  [k][n]
    const float* w   = blockIdx.z == 0 ? wq : (blockIdx.z == 1 ? wk : wv);
    float*      outp = blockIdx.z == 0 ? g_q : (blockIdx.z == 1 ? g_k : g_v);
    const int m0 = blockIdx.y * 128, n0 = blockIdx.x * 128;
    const int tid = threadIdx.x, lane = tid & 31, wid = tid >> 5;
    const int warp_m = (wid & 1) * 64, warp_n = (wid >> 1) * 32;
    const int xm = tid >> 3, xk = (tid & 7) * 4;
    const int n4 = tid & 31, kw = tid >> 5;
    float c[4][4][4] = {};

    for (int k0 = 0; k0 < NIN; k0 += 32) {
        #pragma unroll
        for (int l = 0; l < 4; l++) {
            int m = xm + l * 32;
            float4 v = *(const float4*)&x[(size_t)(m0 + m) * NIN + k0 + xk];
            *(uint4*)&As[m * 36 + xk] =
                make_uint4(cvt_tf32(v.x), cvt_tf32(v.y), cvt_tf32(v.z), cvt_tf32(v.w));
        }
        {
            int gn = n0 + n4 * 4, h = gn >> 6, dh = gn & 63;
            #pragma unroll
            for (int l = 0; l < 4; l++) {
                int kk = kw + l * 8;
                float4 v = *(const float4*)&w[(size_t)h * (NIN * NDH) + (size_t)(k0 + kk) * NDH + dh];
                *(uint4*)&Bs[kk * 132 + n4 * 4] =
                    make_uint4(cvt_tf32(v.x), cvt_tf32(v.y), cvt_tf32(v.z), cvt_tf32(v.w));
            }
        }
        __syncthreads();
        #pragma unroll
        for (int ks = 0; ks < 32; ks += 8) {
            uint32_t a[4][4], b[4][2];
            #pragma unroll
            for (int mt = 0; mt < 4; mt++) ldA(a[mt], As, 36, warp_m + mt * 16, ks, lane);
            #pragma unroll
            for (int nt = 0; nt < 4; nt++) ldBkn(b[nt], Bs, 132, warp_n + nt * 8, ks, lane);
            #pragma unroll
            for (int mt = 0; mt < 4; mt++)
                #pragma unroll
                for (int nt = 0; nt < 4; nt++) mma8(c[mt][nt], a[mt], b[nt]);
        }
        __syncthreads();
    }
    #pragma unroll
    for (int mt = 0; mt < 4; mt++) {
        #pragma unroll
        for (int nt = 0; nt < 4; nt++) {
            int m = m0 + warp_m + mt * 16 + (lane >> 2);
            int n = n0 + warp_n + nt * 8 + 2 * (lane & 3);
            int h = n >> 6, dh = n & 63;
            float* op = outp + (size_t)h * ((size_t)NM * NDH);
            *(float2*)&op[(size_t)m * NDH + dh]       = make_float2(c[mt][nt][0], c[mt][nt][1]);
            *(float2*)&op[(size_t)(m + 8) * NDH + dh] = make_float2(c[mt][nt][2], c[mt][nt][3]);
        }
    }
}

// ---------------------------------------------------------------------------
// K2: denominator, ALL heads in one launch.
// R[h,s,t] = 1 / sum_b exp(q[h,b,s,:].k[h,b,t,:] / 8)
// Block covers s-tile=64, t-tile=128; loops b=0..15 recomputing scores.
// Warp layout 2m x 4n (warp 32x32).  grid (8 t, 16 s, 8 h).
// Dynamic smem: qs[64][68] + ks[128][68] = 52224 B.
// ---------------------------------------------------------------------------
__global__ void __launch_bounds__(256) k_sumR() {
    extern __shared__ uint32_t sh[];
    uint32_t* qs = sh;             // [64][68]
    uint32_t* ks = sh + 64 * 68;   // [128][68]
    const int h = blockIdx.z, s0 = blockIdx.y * 64, t0 = blockIdx.x * 128;
    const int tid = threadIdx.x, lane = tid & 31, wid = tid >> 5;
    const int warp_m = (wid & 1) * 32, warp_n = (wid >> 1) * 32;
    float sum[2][4][4] = {};

    for (int b = 0; b < NB; b++) {
        const size_t base = ((size_t)h * NB + b) * NS * NDH;
        const float* qp = g_q + base;
        const float* kp = g_k + base;
        for (int i = tid; i < 64 * 16; i += 256) {
            int r = i >> 4, c4 = (i & 15) * 4;
            float4 v = *(const float4*)&qp[(size_t)(s0 + r) * NDH + c4];
            *(uint4*)&qs[r * 68 + c4] =
                make_uint4(cvt_tf32(v.x), cvt_tf32(v.y), cvt_tf32(v.z), cvt_tf32(v.w));
        }
        for (int i = tid; i < 128 * 16; i += 256) {
            int r = i >> 4, c4 = (i & 15) * 4;
            float4 v = *(const float4*)&kp[(size_t)(t0 + r) * NDH + c4];
            *(uint4*)&ks[r * 68 + c4] =
                make_uint4(cvt_tf32(v.x), cvt_tf32(v.y), cvt_tf32(v.z), cvt_tf32(v.w));
        }
        __syncthreads();
        float c[2][4][4] = {};
        #pragma unroll
        for (int ksb = 0; ksb < NDH; ksb += 8) {
            uint32_t a[2][4], bb[4][2];
            #pragma unroll
            for (int mt = 0; mt < 2; mt++) ldA(a[mt], qs, 68, warp_m + mt * 16, ksb, lane);
            #pragma unroll
            for (int nt = 0; nt < 4; nt++) ldBnk(bb[nt], ks, 68, warp_n + nt * 8, ksb, lane);
            #pragma unroll
            for (int mt = 0; mt < 2; mt++)
                #pragma unroll
                for (int nt = 0; nt < 4; nt++) mma8(c[mt][nt], a[mt], bb[nt]);
        }
        #pragma unroll
        for (int mt = 0; mt < 2; mt++)
            #pragma unroll
            for (int nt = 0; nt < 4; nt++)
                #pragma unroll
                for (int i = 0; i < 4; i++)
                    sum[mt][nt][i] += __expf(c[mt][nt][i] * 0.125f);
        __syncthreads();
    }
    float* rp = g_R + (size_t)h * NS * NS;
    #pragma unroll
    for (int mt = 0; mt < 2; mt++) {
        #pragma unroll
        for (int nt = 0; nt < 4; nt++) {
            int s = s0 + warp_m + mt * 16 + (lane >> 2);
            int t = t0 + warp_n + nt * 8 + 2 * (lane & 3);
            *(float2*)&rp[(size_t)s * NS + t] =
                make_float2(1.f / sum[mt][nt][0], 1.f / sum[mt][nt][1]);
            *(float2*)&rp[(size_t)(s + 8) * NS + t] =
                make_float2(1.f / sum[mt][nt][2], 1.f / sum[mt][nt][3]);
        }
    }
}

// ---------------------------------------------------------------------------
// K3: fused attention, ALL heads.  For each (s-tile=128, b, h):
// loop t-tiles of 128: recompute scores (identical mma chain to k_sumR),
// exp, multiply by R (L2-resident), round-trip weights through smem as tf32,
// AV-mma into 128x64 accumulators.  Direct stores to g_att — no atomics.
// Scores warps 2m x 4n (64x32); AV warps 4m x 2n (32x32).
// grid (8 s, 16 b, 8 h).  Dynamic smem: qs+kvs (128x68) + Es (128x132) = 137216 B.
// ---------------------------------------------------------------------------
__global__ void __launch_bounds__(256) k_attn() {
    extern __shared__ uint32_t sh[];
    uint32_t* qs  = sh;                  // [128][68]  q tile (persistent)
    uint32_t* kvs = sh + 128 * 68;       // [128][68]  k tile then v tile
    uint32_t* Es  = sh + 2 * 128 * 68;   // [128][132] softmax-weight tile
    const int h = blockIdx.z, b = blockIdx.y, s0 = blockIdx.x * 128;
    const size_t base = ((size_t)h * NB + b) * NS * NDH;
    const float* qp = g_q + base;
    const float* kp = g_k + base;
    const float* vp = g_v + base;
    const float* rp = g_R + (size_t)h * NS * NS;
    const int tid = threadIdx.x, lane = tid & 31, wid = tid >> 5;
    const int wm1 = (wid & 1) * 64, wn1 = (wid >> 1) * 32;   // scores warp tile
    const int wm2 = (wid & 3) * 32, wn2 = (wid >> 2) * 32;   // AV warp tile

    for (int i = tid; i < 128 * 16; i += 256) {
        int r = i >> 4, c4 = (i & 15) * 4;
        float4 v = *(const float4*)&qp[(size_t)(s0 + r) * NDH + c4];
        *(uint4*)&qs[r * 68 + c4] =
            make_uint4(cvt_tf32(v.x), cvt_tf32(v.y), cvt_tf32(v.z), cvt_tf32(v.w));
    }
    __syncthreads();

    float av[2][4][4] = {};
    for (int t0 = 0; t0 < NS; t0 += 128) {
        // load K tile
        for (int i = tid; i < 128 * 16; i += 256) {
            int r = i >> 4, c4 = (i & 15) * 4;
            float4 v = *(const float4*)&kp[(size_t)(t0 + r) * NDH + c4];
            *(uint4*)&kvs[r * 68 + c4] =
                make_uint4(cvt_tf32(v.x), cvt_tf32(v.y), cvt_tf32(v.z), cvt_tf32(v.w));
        }
        __syncthreads();
        // scores mma (same chain as k_sumR -> identical E values)
        float sc[4][4][4] = {};
        #pragma unroll
        for (int ksb = 0; ksb < NDH; ksb += 8) {
            uint32_t a[4][4], bb[4][2];
            #pragma unroll
            for (int mt = 0; mt < 4; mt++) ldA(a[mt], qs, 68, wm1 + mt * 16, ksb, lane);
            #pragma unroll
            for (int nt = 0; nt < 4; nt++) ldBnk(bb[nt], kvs, 68, wn1 + nt * 8, ksb, lane);
            #pragma unroll
            for (int mt = 0; mt < 4; mt++)
                #pragma unroll
                for (int nt = 0; nt < 4; nt++) mma8(sc[mt][nt], a[mt], bb[nt]);
        }
        __syncthreads();   // all scores reads of kvs done
        // exp * R -> Es (tf32);  load V tile into kvs
        #pragma unroll
        for (int mt = 0; mt < 4; mt++) {
            #pragma unroll
            for (int nt = 0; nt < 4; nt++) {
                int sl = wm1 + mt * 16 + (lane >> 2);
                int tl = wn1 + nt * 8 + 2 * (lane & 3);
                float2 r0 = *(const float2*)&rp[(size_t)(s0 + sl) * NS + t0 + tl];
                float2 r1 = *(const float2*)&rp[(size_t)(s0 + sl + 8) * NS + t0 + tl];
                uint32_t e0 = cvt_tf32(__expf(sc[mt][nt][0] * 0.125f) * r0.x);
                uint32_t e1 = cvt_tf32(__expf(sc[mt][nt][1] * 0.125f) * r0.y);
                uint32_t e2 = cvt_tf32(__expf(sc[mt][nt][2] * 0.125f) * r1.x);
                uint32_t e3 = cvt_tf32(__expf(sc[mt][nt][3] * 0.125f) * r1.y);
                *(uint2*)&Es[sl * 132 + tl]       = make_uint2(e0, e1);
                *(uint2*)&Es[(sl + 8) * 132 + tl] = make_uint2(e2, e3);
            }
        }
        for (int i = tid; i < 128 * 16; i += 256) {
            int r = i >> 4, c4 = (i & 15) * 4;
            float4 v = *(const float4*)&vp[(size_t)(t0 + r) * NDH + c4];
            *(uint4*)&kvs[r * 68 + c4] =
                make_uint4(cvt_tf32(v.x), cvt_tf32(v.y), cvt_tf32(v.z), cvt_tf32(v.w));
        }
        __syncthreads();
        // AV mma: A = Es [s][t] (K = t), B = kvs [t][d]
        #pragma unroll
        for (int ksb = 0; ksb < 128; ksb += 8) {
            uint32_t a[2][4], bb[4][2];
            #pragma unroll
            for (int mt = 0; mt < 2; mt++) ldA(a[mt], Es, 132, wm2 + mt * 16, ksb, lane);
            #pragma unroll
            for (int nt = 0; nt < 4; nt++) ldBkn(bb[nt], kvs, 68, wn2 + nt * 8, ksb, lane);
            #pragma unroll
            for (int mt = 0; mt < 2; mt++)
                #pragma unroll
                for (int nt = 0; nt < 4; nt++) mma8(av[mt][nt], a[mt], bb[nt]);
        }
        __syncthreads();   // AV reads done before next k overwrite
    }
    #pragma unroll
    for (int mt = 0; mt < 2; mt++) {
        #pragma unroll
        for (int nt = 0; nt < 4; nt++) {
            int m = s0 + wm2 + mt * 16 + (lane >> 2);
            int d = wn2 + nt * 8 + 2 * (lane & 3);
            float* dst = &g_att[(size_t)(b * NS + m) * NOUT + h * 64 + d];
            *(float2*)dst = make_float2(av[mt][nt][0], av[mt][nt][1]);
            *(float2*)&g_att[(size_t)(b * NS + m + 8) * NOUT + h * 64 + d] =
                make_float2(av[mt][nt][2], av[mt][nt][3]);
        }
    }
}

// ---------------------------------------------------------------------------
// K5: output projection (tf32 mma).  y = att @ w_out + b_out (y into g_R)
// ---------------------------------------------------------------------------
__global__ void __launch_bounds__(256) k_proj(const float* __restrict__ w,
                                              const float* __restrict__ bias) {
    __shared__ __align__(16) uint32_t As[128 * 36];   // att tile [m][k]
    __shared__ __align__(16) uint32_t Bs[32 * 132];   // w tile   [k][n]
    const int m0 = blockIdx.y * 128, n0 = blockIdx.x * 128;
    const int tid = threadIdx.x, lane = tid & 31, wid = tid >> 5;
    const int warp_m = (wid & 1) * 64, warp_n = (wid >> 1) * 32;
    const int xm = tid >> 3, xk = (tid & 7) * 4;
    const int n4 = tid & 31, kw = tid >> 5;
    float c[4][4][4] = {};

    for (int k0 = 0; k0 < NOUT; k0 += 32) {
        #pragma unroll
        for (int l = 0; l < 4; l++) {
            int m = xm + l * 32;
            float4 v = *(const float4*)&g_att[(size_t)(m0 + m) * NOUT + k0 + xk];
            *(uint4*)&As[m * 36 + xk] =
                make_uint4(cvt_tf32(v.x), cvt_tf32(v.y), cvt_tf32(v.z), cvt_tf32(v.w));
        }
        #pragma unroll
        for (int l = 0; l < 4; l++) {
            int kk = kw + l * 8;
            float4 v = *(const float4*)&w[(size_t)(k0 + kk) * NOUT + n0 + n4 * 4];
            *(uint4*)&Bs[kk * 132 + n4 * 4] =
                make_uint4(cvt_tf32(v.x), cvt_tf32(v.y), cvt_tf32(v.z), cvt_tf32(v.w));
        }
        __syncthreads();
        #pragma unroll
        for (int ks = 0; ks < 32; ks += 8) {
            uint32_t a[4][4], b2[4][2];
            #pragma unroll
            for (int mt = 0; mt < 4; mt++) ldA(a[mt], As, 36, warp_m + mt * 16, ks, lane);
            #pragma unroll
            for (int nt = 0; nt < 4; nt++) ldBkn(b2[nt], Bs, 132, warp_n + nt * 8, ks, lane);
            #pragma unroll
            for (int mt = 0; mt < 4; mt++)
                #pragma unroll
                for (int nt = 0; nt < 4; nt++) mma8(c[mt][nt], a[mt], b2[nt]);
        }
        __syncthreads();
    }
    float* yp = g_R;   // reuse g_R as pre-LN output (R is dead)
    #pragma unroll
    for (int mt = 0; mt < 4; mt++) {
        #pragma unroll
        for (int nt = 0; nt < 4; nt++) {
            int m = m0 + warp_m + mt * 16 + (lane >> 2);
            int n = n0 + warp_n + nt * 8 + 2 * (lane & 3);
            float b0 = bias[n], b1 = bias[n + 1];
            *(float2*)&yp[(size_t)m * NOUT + n] =
                make_float2(c[mt][nt][0] + b0, c[mt][nt][1] + b1);
            *(float2*)&yp[(size_t)(m + 8) * NOUT + n] =
                make_float2(c[mt][nt][2] + b0, c[mt][nt][3] + b1);
        }
    }
}

// ---------------------------------------------------------------------------
// K6: LayerNorm + LeakyReLU(0.1).  One block per row (reads y from g_R).
// ---------------------------------------------------------------------------
__global__ void k_ln(const float* __restrict__ gamma, const float* __restrict__ beta,
                     float* __restrict__ out) {
    const int row = blockIdx.x;
    const float* yp = g_R + (size_t)row * NOUT;
    const int tid = threadIdx.x;
    float v0 = yp[tid], v1 = yp[tid + 256];
    float s = v0 + v1, sq = v0 * v0 + v1 * v1;

    __shared__ float red[8], red2[8], stat[2];
    #pragma unroll
    for (int o = 16; o > 0; o >>= 1) {
        s  += __shfl_xor_sync(0xFFFFFFFFu, s,  o);
        sq += __shfl_xor_sync(0xFFFFFFFFu, sq, o);
    }
    int wid = tid >> 5, lane = tid & 31;
    if (lane == 0) { red[wid] = s; red2[wid] = sq; }
    __syncthreads();
    if (tid == 0) {
        float S = 0.f, Q = 0.f;
        #pragma unroll
        for (int i = 0; i < 8; i++) { S += red[i]; Q += red2[i]; }
        float mu  = S * (1.0f / NOUT);
        float var = Q * (1.0f / NOUT) - mu * mu;
        stat[0] = mu;
        stat[1] = rsqrtf(var + 1e-5f);
    }
    __syncthreads();
    float mu = stat[0], rv = stat[1];

    float t0 = (v0 - mu) * rv * gamma[tid]       + beta[tid];
    float t1 = (v1 - mu) * rv * gamma[tid + 256] + beta[tid + 256];
    t0 = t0 >= 0.f ? t0 : 0.1f * t0;
    t1 = t1 >= 0.f ? t1 : 0.1f * t1;
    out[(size_t)row * NOUT + tid]       = t0;
    out[(size_t)row * NOUT + tid + 256] = t1;
}

// ---------------------------------------------------------------------------
constexpr int SMEM_SUMR = (64 * 68 + 128 * 68) * 4;                 // 52224
constexpr int SMEM_ATTN = (2 * 128 * 68 + 128 * 132) * 4;           // 137216

extern "C" void kernel_launch(void* const* d_in, const int* in_sizes, int n_in,
                              void* d_out, int out_size) {
    const float* x     = (const float*)d_in[0];
    const float* wq    = (const float*)d_in[1];
    const float* wk    = (const float*)d_in[2];
    const float* wv    = (const float*)d_in[3];
    const float* w_out = (const float*)d_in[4];
    const float* b_out = (const float*)d_in[5];
    const float* gamma = (const float*)d_in[6];
    const float* beta  = (const float*)d_in[7];
    float* out = (float*)d_out;

    cudaFuncSetAttribute(k_sumR, cudaFuncAttributeMaxDynamicSharedMemorySize, SMEM_SUMR);
    cudaFuncSetAttribute(k_attn, cudaFuncAttributeMaxDynamicSharedMemorySize, SMEM_ATTN);

    k_qkv <<<dim3(NOUT / 128, NM / 128, 3), 256>>>(x, wq, wk, wv);
    k_sumR<<<dim3(NS / 128, NS / 64, NH), 256, SMEM_SUMR>>>();
    k_attn<<<dim3(NS / 128, NB, NH), 256, SMEM_ATTN>>>();
    k_proj<<<dim3(NOUT / 128, NM / 128), 256>>>(w_out, b_out);
    k_ln  <<<NM, 256>>>(gamma, beta, out);
}